// round 15
// baseline (speedup 1.0000x reference)
#include <cuda_runtime.h>
#include <cuda_fp16.h>
#include <cstdint>
#include <math.h>

// ---------------- problem constants ----------------
#define TOTAL    4096
#define DDIM     512
#define DSTRIDE  576          // row stride in halves (1152B) — NOT a power of 2:
                              // keeps the strided tile loads spread across L2 sets
#define NPAIRS   2048
#define NT       32           // 4096/128 tile grid
#define NTILES   528          // NT*(NT+1)/2 upper-triangular tiles
#define NOFFD    496          // off-diagonal tiles (processed first)
#define BT       128
#define KCHUNK   64           // f16 elems per K chunk (128 bytes per smem row)
#define NCHUNKS  8            // 512 / 64
#define NPERSIST 444          // 148 SMs x 3 CTAs — one full resident wave
#define INV_T    (1.0f/0.07f)
// sqrt( (1/0.07) * log2(e) ): operands pre-scaled so accumulator is log2-units
#define SCALE_LOG2 4.539816f

// ---------------- device scratch ----------------
__device__ __half g_emb[TOTAL * DSTRIDE];  // normalized * SCALE_LOG2, f16
__device__ float  g_pos[NPAIRS];
__device__ double g_neg;
__device__ int    g_cnt;
__device__ int    g_tile;
__device__ int    g_prep;     // grid-barrier arrival counter (0 at launch start/end)
__device__ int    g_ack;      // grid-barrier ack counter     (0 at launch start/end)

// ---------------- asm helpers (sm_80-era PTX only) ----------------
__device__ __forceinline__ uint32_t smem_u32(const void* p) {
    return (uint32_t)__cvta_generic_to_shared(p);
}
__device__ __forceinline__ uint32_t h2_bits(__half2 h) {
    return *reinterpret_cast<uint32_t*>(&h);
}
__device__ __forceinline__ void ldmatrix_x4(uint32_t* r, uint32_t addr) {
    asm volatile("ldmatrix.sync.aligned.m8n8.x4.shared.b16 {%0,%1,%2,%3}, [%4];"
        : "=r"(r[0]), "=r"(r[1]), "=r"(r[2]), "=r"(r[3]) : "r"(addr));
}
// f16 accumulate: D (2x f16x2 regs) = A(4) * B(2) + D
__device__ __forceinline__ void mma16816_f16(uint32_t* c, const uint32_t* a,
                                             uint32_t b0, uint32_t b1) {
    asm volatile(
        "mma.sync.aligned.m16n8k16.row.col.f16.f16.f16.f16 "
        "{%0,%1}, {%2,%3,%4,%5}, {%6,%7}, {%0,%1};"
        : "+r"(c[0]), "+r"(c[1])
        : "r"(a[0]), "r"(a[1]), "r"(a[2]), "r"(a[3]), "r"(b0), "r"(b1));
}
#define CP_ASYNC16(so, gp) \
    asm volatile("cp.async.cg.shared.global [%0], [%1], 16;" :: "r"(so), "l"(gp))
#define CP_COMMIT()  asm volatile("cp.async.commit_group;" ::: "memory")
#define CP_WAIT(n)   asm volatile("cp.async.wait_group %0;" :: "n"(n) : "memory")

// fast exp2 with clamp: masked lanes arrive as -1000, clamped to -100 -> ~0
__device__ __forceinline__ float exp2_fast(float tv) {
    tv = fmaxf(tv, -100.0f);
    float rr = tv + 12582912.0f;            // round-to-nearest-int magic (1.5*2^23)
    float kf = rr - 12582912.0f;
    float f  = tv - kf;                     // f in [-0.5, 0.5]
    float p  = fmaf(f, 0.009618129f, 0.05550411f);
    p = fmaf(f, p, 0.24022651f);
    p = fmaf(f, p, 0.69314718f);
    p = fmaf(f, p, 1.0f);                   // ~= 2^f
    return __int_as_float((__float_as_int(rr) << 23) + __float_as_int(p));
}

// ---------------------------------------------------------------------------
// Fused persistent kernel.
// Phase 0 (prep): each CTA normalizes/quantizes ~4.6 augmentation pairs into
//   g_emb (f16, padded 1152B stride) and computes positive-pair logits.
//   CTA 0 also resets the tile/negsum counters.
// Grid barrier: arrival counter + ack counter; the LAST acker (which runs
//   only after every spinner has exited) resets both to 0 for graph replay.
//   Residency of all 444 CTAs is guaranteed: launch_bounds(128,3), 64KB smem.
// Phase 1 (GEMM): persistent tile stealing over 528 upper-triangular 128x128
//   tiles, off-diagonal first / diagonal last (LPT). Per tile: 4 warps of
//   64x64 HMMA f16-acc, 2-stage cp.async, fully unrolled K loop. Diagonal
//   tiles alias B->A and skip warp 1 (strict lower mirror of warp 2; weights
//   w0=w3=0.5, w1=0, w2=1). Label-masked exp2 epilogue; the CTA completing
//   the last tile computes the final loss.
// ---------------------------------------------------------------------------
__device__ __forceinline__ void load_chunk(uint32_t sb, int tid, int row0, int col0,
                                           int c, int buf, bool diag) {
    #pragma unroll
    for (int itv = 0; itv < 16; itv++) {
        int slot = itv * 128 + tid;           // 0..2047 16B transfers
        int isB  = slot >> 10;
        if (isB && diag) break;               // diagonal: B tile aliases A tile
        int s2   = slot & 1023;
        int r    = s2 >> 3;                   // row in tile (0..127)
        int g    = s2 & 7;                    // 16B group in 128B row
        const __half* src = g_emb + (size_t)((isB ? col0 : row0) + r) * DSTRIDE
                          + c * KCHUNK + g * 8;
        uint32_t so = sb + buf * 32768 + isB * 16384
                    + (uint32_t)(r * 128) + (uint32_t)((g * 16) ^ ((r & 7) * 16));
        CP_ASYNC16(so, src);
    }
    CP_COMMIT();
}

__global__ void __launch_bounds__(128, 3) fused_kernel(
        const float* __restrict__ E, const int* __restrict__ labels,
        float* __restrict__ out) {
    extern __shared__ char smem[];
    __shared__ float red[4];
    __shared__ float s_aa[4], s_bb[4], s_ab[4];
    __shared__ int   s_work;
    __shared__ int   lastflag;
    __shared__ int   labR[BT], labC[BT];
    uint32_t sb = smem_u32(smem);

    int tid  = threadIdx.x;
    int lane = tid & 31;
    int wid  = tid >> 5;

    // ================= phase 0: prep =================
    for (int pair = blockIdx.x; pair < NPAIRS; pair += NPERSIST) {
        const float4* A = reinterpret_cast<const float4*>(E + (size_t)(2 * pair) * DDIM);
        const float4* B = A + DDIM / 4;
        float4 a = A[tid], b = B[tid];
        float aa = a.x*a.x + a.y*a.y + a.z*a.z + a.w*a.w;
        float bb = b.x*b.x + b.y*b.y + b.z*b.z + b.w*b.w;
        float ab = a.x*b.x + a.y*b.y + a.z*b.z + a.w*b.w;
        #pragma unroll
        for (int off = 16; off > 0; off >>= 1) {
            aa += __shfl_down_sync(0xffffffffu, aa, off);
            bb += __shfl_down_sync(0xffffffffu, bb, off);
            ab += __shfl_down_sync(0xffffffffu, ab, off);
        }
        if (lane == 0) { s_aa[wid] = aa; s_bb[wid] = bb; s_ab[wid] = ab; }
        __syncthreads();
        float taa = s_aa[0] + s_aa[1] + s_aa[2] + s_aa[3];
        float tbb = s_bb[0] + s_bb[1] + s_bb[2] + s_bb[3];
        float tab = s_ab[0] + s_ab[1] + s_ab[2] + s_ab[3];
        float sa = rsqrtf(taa) * SCALE_LOG2;
        float sb2 = rsqrtf(tbb) * SCALE_LOG2;

        size_t baseA = (size_t)(2 * pair) * DSTRIDE + tid * 4;
        uint2 pa, pb;
        pa.x = h2_bits(__floats2half2_rn(a.x * sa, a.y * sa));
        pa.y = h2_bits(__floats2half2_rn(a.z * sa, a.w * sa));
        pb.x = h2_bits(__floats2half2_rn(b.x * sb2, b.y * sb2));
        pb.y = h2_bits(__floats2half2_rn(b.z * sb2, b.w * sb2));
        *reinterpret_cast<uint2*>(g_emb + baseA) = pa;
        *reinterpret_cast<uint2*>(g_emb + baseA + DSTRIDE) = pb;

        if (tid == 0) g_pos[pair] = tab * rsqrtf(taa * tbb) * INV_T;
        __syncthreads();   // s_aa reuse in next iteration
    }
    if (blockIdx.x == 0 && tid == 0) { g_neg = 0.0; g_cnt = 0; g_tile = 0; }

    // ================= grid barrier =================
    __threadfence();
    __syncthreads();
    if (tid == 0) {
        atomicAdd(&g_prep, 1);
        volatile int* vp = &g_prep;
        while (*vp < NPERSIST) { }
        // last acker runs only after EVERY spinner exited -> reset is race-free
        if (atomicAdd(&g_ack, 1) == NPERSIST - 1) { g_prep = 0; g_ack = 0; }
    }
    __syncthreads();
    __threadfence();

    // ================= phase 1: persistent GEMM =================
    // lane addressing constants (tile-independent)
    int wm0 = (wid & 1) * 64;
    int wn0 = (wid >> 1) * 64;
    int arow = wm0 + (lane & 15);
    uint32_t a_rowoff = (uint32_t)(arow * 128);
    uint32_t a_xor = (uint32_t)((arow & 7) * 16);
    uint32_t a_colbase = (uint32_t)((lane >> 4) * 16);
    int brow = wn0 + ((lane >> 4) & 1) * 8 + (lane & 7);
    uint32_t b_rowoff = (uint32_t)(brow * 128);
    uint32_t b_xor = (uint32_t)((brow & 7) * 16);
    uint32_t b_colbase = (uint32_t)(((lane >> 3) & 1) * 16);
    int rbase = wm0 + (lane >> 2);
    int cbase = wn0 + (lane & 3) * 2;

    for (;;) {
        if (tid == 0) s_work = atomicAdd(&g_tile, 1);
        __syncthreads();
        int w = s_work;
        if (w >= NTILES) break;

        // work order: off-diagonal tiles first (0..495), diagonal last
        int bi, bj;
        if (w < NOFFD) {
            int t = w, rem = NT - 1;
            bi = 0;
            while (t >= rem) { t -= rem; rem--; bi++; }
            bj = bi + 1 + t;
        } else {
            bi = bj = w - NOFFD;
        }
        int row0 = bi * BT, col0 = bj * BT;
        bool diag = (bi == bj);
        bool skipwarp = diag && (wid == 1);   // strict lower mirror of warp 2

        load_chunk(sb, tid, row0, col0, 0, 0, diag);
        load_chunk(sb, tid, row0, col0, 1, 1, diag);

        labR[tid] = labels[(row0 + tid) >> 1];
        labC[tid] = labels[(col0 + tid) >> 1];

        uint32_t acc[4][8][2];                // f16x2 accumulators (64x64)
        #pragma unroll
        for (int i = 0; i < 4; i++)
            #pragma unroll
            for (int j = 0; j < 8; j++) { acc[i][j][0] = 0u; acc[i][j][1] = 0u; }

        #pragma unroll
        for (int c = 0; c < NCHUNKS; c++) {
            const int buf = c & 1;
            if (c == NCHUNKS - 1) { CP_WAIT(0); } else { CP_WAIT(1); }
            __syncthreads();

            if (!skipwarp) {
                uint32_t Ab = sb + (uint32_t)(buf * 32768) + a_rowoff;
                uint32_t Bb = (diag ? sb : sb + 16384u) + (uint32_t)(buf * 32768) + b_rowoff;
                #pragma unroll
                for (int ks = 0; ks < 4; ks++) {
                    uint32_t a[4][4];
                    uint32_t acol = (uint32_t)(ks * 32) + a_colbase;
                    #pragma unroll
                    for (int mt = 0; mt < 4; mt++)
                        ldmatrix_x4(a[mt], Ab + (uint32_t)(mt * 16 * 128) + (acol ^ a_xor));

                    uint32_t b[4][4];
                    uint32_t bcol = (uint32_t)(ks * 32) + b_colbase;
                    #pragma unroll
                    for (int p = 0; p < 4; p++)
                        ldmatrix_x4(b[p], Bb + (uint32_t)(p * 16 * 128) + (bcol ^ b_xor));

                    #pragma unroll
                    for (int mt = 0; mt < 4; mt++)
                        #pragma unroll
                        for (int nt = 0; nt < 8; nt++)
                            mma16816_f16(acc[mt][nt], a[mt],
                                         b[nt >> 1][(nt & 1) * 2 + 0],
                                         b[nt >> 1][(nt & 1) * 2 + 1]);
                }
            }
            if (c + 2 < NCHUNKS) {            // no buffer reuse after last loads
                __syncthreads();
                load_chunk(sb, tid, row0, col0, c + 2, buf, diag);
            }
        }

        // ---- epilogue: label-masked exp2 sum ----
        float ls[4] = {0.0f, 0.0f, 0.0f, 0.0f};
        #pragma unroll
        for (int mt = 0; mt < 4; mt++)
            #pragma unroll
            for (int e = 0; e < 2; e++) {
                int lr = labR[rbase + mt * 16 + e * 8];
                #pragma unroll
                for (int nt = 0; nt < 8; nt++) {
                    float2 v = __half22float2(*reinterpret_cast<__half2*>(&acc[mt][nt][e]));
                    int c0 = labC[cbase + nt * 8];
                    int c1 = labC[cbase + nt * 8 + 1];
                    float m0 = (lr == c0) ? -1000.0f : v.x;
                    float m1 = (lr == c1) ? -1000.0f : v.y;
                    ls[nt & 3] += exp2_fast(m0) + exp2_fast(m1);
                }
            }
        float lsum = (ls[0] + ls[1]) + (ls[2] + ls[3]);
        // diag weights: w0=w3=0.5, w1=0 (skipped mirror), w2=1
        if (diag) lsum *= (wid == 1) ? 0.0f : ((wid == 2) ? 1.0f : 0.5f);

        #pragma unroll
        for (int off = 16; off > 0; off >>= 1)
            lsum += __shfl_down_sync(0xffffffffu, lsum, off);
        if (lane == 0) red[wid] = lsum;
        __syncthreads();
        if (tid == 0) {
            atomicAdd(&g_neg, (double)(red[0] + red[1] + red[2] + red[3]));
            __threadfence();
            lastflag = (atomicAdd(&g_cnt, 1) == NTILES - 1);
        }
        __syncthreads();

        // ---- CTA completing the last tile computes the final loss ----
        if (lastflag) {
            __threadfence();
            float negf = (float)g_neg;
            float s = 0.0f;
            for (int p = tid; p < NPAIRS; p += 128) {
                float sp = g_pos[p];
                s += __logf(__expf(sp) + negf) - sp;
            }
            #pragma unroll
            for (int off = 16; off > 0; off >>= 1)
                s += __shfl_down_sync(0xffffffffu, s, off);
            if (lane == 0) red[wid] = s;
            __syncthreads();
            if (tid == 0)
                out[0] = (red[0] + red[1] + red[2] + red[3]) / (float)NPAIRS;
        }
        __syncthreads();   // protect labR/labC/red before next tile
    }
}

// ---------------------------------------------------------------------------
extern "C" void kernel_launch(void* const* d_in, const int* in_sizes, int n_in,
                              void* d_out, int out_size) {
    const float* E      = (const float*)d_in[0];
    const int*   labels = (const int*)d_in[1];
    float*       out    = (float*)d_out;

    const int SMEM_BYTES = 2 * 32768;   // double-buffered A+B tiles
    cudaFuncSetAttribute(fused_kernel,
                         cudaFuncAttributeMaxDynamicSharedMemorySize, SMEM_BYTES);

    fused_kernel<<<NPERSIST, 128, SMEM_BYTES>>>(E, labels, out);
}

// round 16
// speedup vs baseline: 1.2416x; 1.2416x over previous
#include <cuda_runtime.h>
#include <cuda_fp16.h>
#include <cstdint>
#include <math.h>

// ---------------- problem constants ----------------
#define TOTAL    4096
#define DDIM     512
#define DSTRIDE  576          // row stride in halves (1152B) — NOT a power of 2:
                              // keeps the strided tile loads spread across L2 sets
#define NPAIRS   2048
#define NT       32           // 4096/128 tile grid
#define NTILES   528          // NT*(NT+1)/2 upper-triangular tiles
#define NOFFD    496          // off-diagonal tiles (processed first)
#define BT       128
#define KCHUNK   64           // f16 elems per K chunk (128 bytes per smem row)
#define NCHUNKS  8            // 512 / 64
#define NPERSIST 444          // 148 SMs x 3 CTAs — one full resident wave
#define INV_T    (1.0f/0.07f)
// sqrt( (1/0.07) * log2(e) ): operands pre-scaled so accumulator is log2-units
#define SCALE_LOG2 4.539816f

// ---------------- device scratch ----------------
__device__ __half g_emb[TOTAL * DSTRIDE];  // normalized * SCALE_LOG2, f16
__device__ float  g_pos[NPAIRS];
__device__ double g_neg;
__device__ int    g_cnt;
__device__ int    g_tile;

// ---------------- asm helpers (sm_80-era PTX only) ----------------
__device__ __forceinline__ uint32_t smem_u32(const void* p) {
    return (uint32_t)__cvta_generic_to_shared(p);
}
__device__ __forceinline__ uint32_t h2_bits(__half2 h) {
    return *reinterpret_cast<uint32_t*>(&h);
}
__device__ __forceinline__ void ldmatrix_x4(uint32_t* r, uint32_t addr) {
    asm volatile("ldmatrix.sync.aligned.m8n8.x4.shared.b16 {%0,%1,%2,%3}, [%4];"
        : "=r"(r[0]), "=r"(r[1]), "=r"(r[2]), "=r"(r[3]) : "r"(addr));
}
// f16 accumulate: D (2x f16x2 regs) = A(4) * B(2) + D
__device__ __forceinline__ void mma16816_f16(uint32_t* c, const uint32_t* a,
                                             uint32_t b0, uint32_t b1) {
    asm volatile(
        "mma.sync.aligned.m16n8k16.row.col.f16.f16.f16.f16 "
        "{%0,%1}, {%2,%3,%4,%5}, {%6,%7}, {%0,%1};"
        : "+r"(c[0]), "+r"(c[1])
        : "r"(a[0]), "r"(a[1]), "r"(a[2]), "r"(a[3]), "r"(b0), "r"(b1));
}
#define CP_ASYNC16(so, gp) \
    asm volatile("cp.async.cg.shared.global [%0], [%1], 16;" :: "r"(so), "l"(gp))
#define CP_COMMIT()  asm volatile("cp.async.commit_group;" ::: "memory")
#define CP_WAIT(n)   asm volatile("cp.async.wait_group %0;" :: "n"(n) : "memory")

// fast exp2 with clamp: masked lanes arrive as -1000, clamped to -100 -> ~0
__device__ __forceinline__ float exp2_fast(float tv) {
    tv = fmaxf(tv, -100.0f);
    float rr = tv + 12582912.0f;            // round-to-nearest-int magic (1.5*2^23)
    float kf = rr - 12582912.0f;
    float f  = tv - kf;                     // f in [-0.5, 0.5]
    float p  = fmaf(f, 0.009618129f, 0.05550411f);
    p = fmaf(f, p, 0.24022651f);
    p = fmaf(f, p, 0.69314718f);
    p = fmaf(f, p, 1.0f);                   // ~= 2^f
    return __int_as_float((__float_as_int(rr) << 23) + __float_as_int(p));
}

// ---------------------------------------------------------------------------
// 1) prep+pos: one block per augmentation pair (rows 2p, 2p+1).
//    Normalize, scale by sqrt(log2e/T), cast f16 into the padded operand
//    array; compute the positive-pair logit in fp32. 2048 independent CTAs
//    give full memory-level parallelism (fusing this into the persistent
//    kernel was measured 9us slower — R15).
// ---------------------------------------------------------------------------
__global__ void prep_kernel(const float* __restrict__ E) {
    int pair = blockIdx.x;
    int tid  = threadIdx.x;       // 128 threads
    int lane = tid & 31, wid = tid >> 5;

    const float4* A = reinterpret_cast<const float4*>(E + (size_t)(2 * pair) * DDIM);
    const float4* B = A + DDIM / 4;
    float4 a = A[tid], b = B[tid];
    float aa = a.x*a.x + a.y*a.y + a.z*a.z + a.w*a.w;
    float bb = b.x*b.x + b.y*b.y + b.z*b.z + b.w*b.w;
    float ab = a.x*b.x + a.y*b.y + a.z*b.z + a.w*b.w;
    #pragma unroll
    for (int off = 16; off > 0; off >>= 1) {
        aa += __shfl_down_sync(0xffffffffu, aa, off);
        bb += __shfl_down_sync(0xffffffffu, bb, off);
        ab += __shfl_down_sync(0xffffffffu, ab, off);
    }
    __shared__ float s_aa[4], s_bb[4], s_ab[4];
    if (lane == 0) { s_aa[wid] = aa; s_bb[wid] = bb; s_ab[wid] = ab; }
    __syncthreads();
    float taa = s_aa[0] + s_aa[1] + s_aa[2] + s_aa[3];
    float tbb = s_bb[0] + s_bb[1] + s_bb[2] + s_bb[3];
    float tab = s_ab[0] + s_ab[1] + s_ab[2] + s_ab[3];
    float sa = rsqrtf(taa) * SCALE_LOG2;
    float sb = rsqrtf(tbb) * SCALE_LOG2;

    size_t baseA = (size_t)(2 * pair) * DSTRIDE + tid * 4;
    uint2 pa, pb;
    pa.x = h2_bits(__floats2half2_rn(a.x * sa, a.y * sa));
    pa.y = h2_bits(__floats2half2_rn(a.z * sa, a.w * sa));
    pb.x = h2_bits(__floats2half2_rn(b.x * sb, b.y * sb));
    pb.y = h2_bits(__floats2half2_rn(b.z * sb, b.w * sb));
    *reinterpret_cast<uint2*>(g_emb + baseA) = pa;
    *reinterpret_cast<uint2*>(g_emb + baseA + DSTRIDE) = pb;

    if (tid == 0) {
        g_pos[pair] = tab * rsqrtf(taa * tbb) * INV_T;
        if (pair == 0) { g_neg = 0.0; g_cnt = 0; g_tile = 0; }
    }
}

// ---------------------------------------------------------------------------
// 2) Persistent HMMA f16-acc GEMM: 444 CTAs (3/SM) steal 128x128 tiles from a
//    global counter — no low-occupancy second wave. Off-diagonal tiles first,
//    diagonal last (LPT: diag tiles are ~75% cost). Per tile: 4 warps of
//    64x64, 2-stage cp.async, fully unrolled K loop, padded 1152B row stride.
//    Diagonal tiles alias B->A and skip warp 1 (strict lower mirror of warp
//    2's subtile; weights w0=w3=0.5, w1=0, w2=1). Arithmetic label mask +
//    exp2 epilogue. CTA completing the last tile computes the final loss.
// ---------------------------------------------------------------------------
__device__ __forceinline__ void load_chunk(uint32_t sb, int tid, int row0, int col0,
                                           int c, int buf, bool diag) {
    #pragma unroll
    for (int itv = 0; itv < 16; itv++) {
        int slot = itv * 128 + tid;           // 0..2047 16B transfers
        int isB  = slot >> 10;
        if (isB && diag) break;               // diagonal: B tile aliases A tile
        int s2   = slot & 1023;
        int r    = s2 >> 3;                   // row in tile (0..127)
        int g    = s2 & 7;                    // 16B group in 128B row
        const __half* src = g_emb + (size_t)((isB ? col0 : row0) + r) * DSTRIDE
                          + c * KCHUNK + g * 8;
        uint32_t so = sb + buf * 32768 + isB * 16384
                    + (uint32_t)(r * 128) + (uint32_t)((g * 16) ^ ((r & 7) * 16));
        CP_ASYNC16(so, src);
    }
    CP_COMMIT();
}

__global__ void __launch_bounds__(128, 3) gemm_negsum_kernel(
        const int* __restrict__ labels, float* __restrict__ out) {
    extern __shared__ char smem[];
    __shared__ float red[4];
    __shared__ int   s_work;
    __shared__ int   lastflag;
    __shared__ int   labR[BT], labC[BT];
    uint32_t sb = smem_u32(smem);

    int tid  = threadIdx.x;
    int lane = tid & 31;
    int wid  = tid >> 5;

    // lane addressing constants (tile-independent)
    int wm0 = (wid & 1) * 64;
    int wn0 = (wid >> 1) * 64;
    int arow = wm0 + (lane & 15);
    uint32_t a_rowoff = (uint32_t)(arow * 128);
    uint32_t a_xor = (uint32_t)((arow & 7) * 16);
    uint32_t a_colbase = (uint32_t)((lane >> 4) * 16);
    int brow = wn0 + ((lane >> 4) & 1) * 8 + (lane & 7);
    uint32_t b_rowoff = (uint32_t)(brow * 128);
    uint32_t b_xor = (uint32_t)((brow & 7) * 16);
    uint32_t b_colbase = (uint32_t)(((lane >> 3) & 1) * 16);
    int rbase = wm0 + (lane >> 2);
    int cbase = wn0 + (lane & 3) * 2;

    for (;;) {
        if (tid == 0) s_work = atomicAdd(&g_tile, 1);
        __syncthreads();
        int w = s_work;
        if (w >= NTILES) break;

        // work order: off-diagonal tiles first (0..495), diagonal last
        int bi, bj;
        if (w < NOFFD) {
            int t = w, rem = NT - 1;
            bi = 0;
            while (t >= rem) { t -= rem; rem--; bi++; }
            bj = bi + 1 + t;
        } else {
            bi = bj = w - NOFFD;
        }
        int row0 = bi * BT, col0 = bj * BT;
        bool diag = (bi == bj);
        bool skipwarp = diag && (wid == 1);   // strict lower mirror of warp 2

        load_chunk(sb, tid, row0, col0, 0, 0, diag);
        load_chunk(sb, tid, row0, col0, 1, 1, diag);

        labR[tid] = labels[(row0 + tid) >> 1];
        labC[tid] = labels[(col0 + tid) >> 1];

        uint32_t acc[4][8][2];                // f16x2 accumulators (64x64)
        #pragma unroll
        for (int i = 0; i < 4; i++)
            #pragma unroll
            for (int j = 0; j < 8; j++) { acc[i][j][0] = 0u; acc[i][j][1] = 0u; }

        #pragma unroll
        for (int c = 0; c < NCHUNKS; c++) {
            const int buf = c & 1;
            if (c == NCHUNKS - 1) { CP_WAIT(0); } else { CP_WAIT(1); }
            __syncthreads();

            if (!skipwarp) {
                uint32_t Ab = sb + (uint32_t)(buf * 32768) + a_rowoff;
                uint32_t Bb = (diag ? sb : sb + 16384u) + (uint32_t)(buf * 32768) + b_rowoff;
                #pragma unroll
                for (int ks = 0; ks < 4; ks++) {
                    uint32_t a[4][4];
                    uint32_t acol = (uint32_t)(ks * 32) + a_colbase;
                    #pragma unroll
                    for (int mt = 0; mt < 4; mt++)
                        ldmatrix_x4(a[mt], Ab + (uint32_t)(mt * 16 * 128) + (acol ^ a_xor));

                    uint32_t b[4][4];
                    uint32_t bcol = (uint32_t)(ks * 32) + b_colbase;
                    #pragma unroll
                    for (int p = 0; p < 4; p++)
                        ldmatrix_x4(b[p], Bb + (uint32_t)(p * 16 * 128) + (bcol ^ b_xor));

                    #pragma unroll
                    for (int mt = 0; mt < 4; mt++)
                        #pragma unroll
                        for (int nt = 0; nt < 8; nt++)
                            mma16816_f16(acc[mt][nt], a[mt],
                                         b[nt >> 1][(nt & 1) * 2 + 0],
                                         b[nt >> 1][(nt & 1) * 2 + 1]);
                }
            }
            if (c + 2 < NCHUNKS) {            // no buffer reuse after last loads
                __syncthreads();
                load_chunk(sb, tid, row0, col0, c + 2, buf, diag);
            }
        }

        // ---- epilogue: label-masked exp2 sum ----
        float ls[4] = {0.0f, 0.0f, 0.0f, 0.0f};
        #pragma unroll
        for (int mt = 0; mt < 4; mt++)
            #pragma unroll
            for (int e = 0; e < 2; e++) {
                int lr = labR[rbase + mt * 16 + e * 8];
                #pragma unroll
                for (int nt = 0; nt < 8; nt++) {
                    float2 v = __half22float2(*reinterpret_cast<__half2*>(&acc[mt][nt][e]));
                    int c0 = labC[cbase + nt * 8];
                    int c1 = labC[cbase + nt * 8 + 1];
                    float m0 = (lr == c0) ? -1000.0f : v.x;
                    float m1 = (lr == c1) ? -1000.0f : v.y;
                    ls[nt & 3] += exp2_fast(m0) + exp2_fast(m1);
                }
            }
        float lsum = (ls[0] + ls[1]) + (ls[2] + ls[3]);
        // diag weights: w0=w3=0.5, w1=0 (skipped mirror), w2=1
        if (diag) lsum *= (wid == 1) ? 0.0f : ((wid == 2) ? 1.0f : 0.5f);

        #pragma unroll
        for (int off = 16; off > 0; off >>= 1)
            lsum += __shfl_down_sync(0xffffffffu, lsum, off);
        if (lane == 0) red[wid] = lsum;
        __syncthreads();
        if (tid == 0) {
            atomicAdd(&g_neg, (double)(red[0] + red[1] + red[2] + red[3]));
            __threadfence();
            lastflag = (atomicAdd(&g_cnt, 1) == NTILES - 1);
        }
        __syncthreads();

        // ---- CTA completing the last tile computes the final loss ----
        if (lastflag) {
            __threadfence();
            float negf = (float)g_neg;
            float s = 0.0f;
            for (int p = tid; p < NPAIRS; p += 128) {
                float sp = g_pos[p];
                s += __logf(__expf(sp) + negf) - sp;
            }
            #pragma unroll
            for (int off = 16; off > 0; off >>= 1)
                s += __shfl_down_sync(0xffffffffu, s, off);
            if (lane == 0) red[wid] = s;
            __syncthreads();
            if (tid == 0)
                out[0] = (red[0] + red[1] + red[2] + red[3]) / (float)NPAIRS;
        }
        __syncthreads();   // protect labR/labC/red before next tile
    }
}

// ---------------------------------------------------------------------------
extern "C" void kernel_launch(void* const* d_in, const int* in_sizes, int n_in,
                              void* d_out, int out_size) {
    const float* E      = (const float*)d_in[0];
    const int*   labels = (const int*)d_in[1];
    float*       out    = (float*)d_out;

    const int SMEM_BYTES = 2 * 32768;   // double-buffered A+B tiles
    cudaFuncSetAttribute(gemm_negsum_kernel,
                         cudaFuncAttributeMaxDynamicSharedMemorySize, SMEM_BYTES);

    prep_kernel<<<NPAIRS, 128>>>(E);
    gemm_negsum_kernel<<<NPERSIST, 128, SMEM_BYTES>>>(labels, out);
}

// round 17
// speedup vs baseline: 1.2682x; 1.0214x over previous
#include <cuda_runtime.h>
#include <cuda_fp16.h>
#include <cstdint>
#include <math.h>

// ---------------- problem constants ----------------
#define TOTAL    4096
#define DDIM     512
#define DSTRIDE  576          // row stride in halves (1152B) — NOT a power of 2:
                              // keeps the strided tile loads spread across L2 sets
#define NPAIRS   2048
#define NT       32           // 4096/128 tile grid
#define NTILES   528          // NT*(NT+1)/2 upper-triangular tiles
#define NOFFD    496          // off-diagonal tiles (processed first)
#define BT       128
#define KCHUNK   64           // f16 elems per K chunk (128 bytes per smem row)
#define NCHUNKS  8            // 512 / 64
#define NPERSIST 444          // 148 SMs x 3 CTAs — one full resident wave
#define INV_T    (1.0f/0.07f)
// sqrt( (1/0.07) * log2(e) ): operands pre-scaled so accumulator is log2-units
#define SCALE_LOG2 4.539816f
#define MASKVAL  (-126.0f)    // masked sentinel: exp2(-126) ~ 1e-38, normal, no clamp

// ---------------- device scratch ----------------
__device__ __half g_emb[TOTAL * DSTRIDE];  // normalized * SCALE_LOG2, f16
__device__ float  g_pos[NPAIRS];
__device__ double g_neg;
__device__ int    g_cnt;
__device__ int    g_tile;

// ---------------- asm helpers (sm_80-era PTX only) ----------------
__device__ __forceinline__ uint32_t smem_u32(const void* p) {
    return (uint32_t)__cvta_generic_to_shared(p);
}
__device__ __forceinline__ uint32_t h2_bits(__half2 h) {
    return *reinterpret_cast<uint32_t*>(&h);
}
__device__ __forceinline__ void ldmatrix_x4(uint32_t* r, uint32_t addr) {
    asm volatile("ldmatrix.sync.aligned.m8n8.x4.shared.b16 {%0,%1,%2,%3}, [%4];"
        : "=r"(r[0]), "=r"(r[1]), "=r"(r[2]), "=r"(r[3]) : "r"(addr));
}
// f16 accumulate: D (2x f16x2 regs) = A(4) * B(2) + D
__device__ __forceinline__ void mma16816_f16(uint32_t* c, const uint32_t* a,
                                             uint32_t b0, uint32_t b1) {
    asm volatile(
        "mma.sync.aligned.m16n8k16.row.col.f16.f16.f16.f16 "
        "{%0,%1}, {%2,%3,%4,%5}, {%6,%7}, {%0,%1};"
        : "+r"(c[0]), "+r"(c[1])
        : "r"(a[0]), "r"(a[1]), "r"(a[2]), "r"(a[3]), "r"(b0), "r"(b1));
}
#define CP_ASYNC16(so, gp) \
    asm volatile("cp.async.cg.shared.global [%0], [%1], 16;" :: "r"(so), "l"(gp))
#define CP_COMMIT()  asm volatile("cp.async.commit_group;" ::: "memory")
#define CP_WAIT(n)   asm volatile("cp.async.wait_group %0;" :: "n"(n) : "memory")

// fast exp2, NO clamp: inputs are either true logits (|x| <= ~21) or the
// -126 mask sentinel, both safely inside the trick's range.
__device__ __forceinline__ float exp2_fast(float tv) {
    float rr = tv + 12582912.0f;            // round-to-nearest-int magic (1.5*2^23)
    float kf = rr - 12582912.0f;
    float f  = tv - kf;                     // f in [-0.5, 0.5]
    float p  = fmaf(f, 0.009618129f, 0.05550411f);
    p = fmaf(f, p, 0.24022651f);
    p = fmaf(f, p, 0.69314718f);
    p = fmaf(f, p, 1.0f);                   // ~= 2^f
    return __int_as_float((__float_as_int(rr) << 23) + __float_as_int(p));
}

// ---------------------------------------------------------------------------
// 1) prep+pos: one block per augmentation pair (rows 2p, 2p+1).
//    Normalize, scale by sqrt(log2e/T), cast f16 into the padded operand
//    array; compute the positive-pair logit in fp32. 2048 independent CTAs
//    give full memory-level parallelism (fusing this into the persistent
//    kernel was measured 9us slower — R15).
// ---------------------------------------------------------------------------
__global__ void prep_kernel(const float* __restrict__ E) {
    int pair = blockIdx.x;
    int tid  = threadIdx.x;       // 128 threads
    int lane = tid & 31, wid = tid >> 5;

    const float4* A = reinterpret_cast<const float4*>(E + (size_t)(2 * pair) * DDIM);
    const float4* B = A + DDIM / 4;
    float4 a = A[tid], b = B[tid];
    float aa = a.x*a.x + a.y*a.y + a.z*a.z + a.w*a.w;
    float bb = b.x*b.x + b.y*b.y + b.z*b.z + b.w*b.w;
    float ab = a.x*b.x + a.y*b.y + a.z*b.z + a.w*b.w;
    #pragma unroll
    for (int off = 16; off > 0; off >>= 1) {
        aa += __shfl_down_sync(0xffffffffu, aa, off);
        bb += __shfl_down_sync(0xffffffffu, bb, off);
        ab += __shfl_down_sync(0xffffffffu, ab, off);
    }
    __shared__ float s_aa[4], s_bb[4], s_ab[4];
    if (lane == 0) { s_aa[wid] = aa; s_bb[wid] = bb; s_ab[wid] = ab; }
    __syncthreads();
    float taa = s_aa[0] + s_aa[1] + s_aa[2] + s_aa[3];
    float tbb = s_bb[0] + s_bb[1] + s_bb[2] + s_bb[3];
    float tab = s_ab[0] + s_ab[1] + s_ab[2] + s_ab[3];
    float sa = rsqrtf(taa) * SCALE_LOG2;
    float sb = rsqrtf(tbb) * SCALE_LOG2;

    size_t baseA = (size_t)(2 * pair) * DSTRIDE + tid * 4;
    uint2 pa, pb;
    pa.x = h2_bits(__floats2half2_rn(a.x * sa, a.y * sa));
    pa.y = h2_bits(__floats2half2_rn(a.z * sa, a.w * sa));
    pb.x = h2_bits(__floats2half2_rn(b.x * sb, b.y * sb));
    pb.y = h2_bits(__floats2half2_rn(b.z * sb, b.w * sb));
    *reinterpret_cast<uint2*>(g_emb + baseA) = pa;
    *reinterpret_cast<uint2*>(g_emb + baseA + DSTRIDE) = pb;

    if (tid == 0) {
        g_pos[pair] = tab * rsqrtf(taa * tbb) * INV_T;
        if (pair == 0) { g_neg = 0.0; g_cnt = 0; g_tile = 0; }
    }
}

// ---------------------------------------------------------------------------
// 2) Persistent HMMA f16-acc GEMM: 444 CTAs (3/SM) steal 128x128 tiles from a
//    global counter — no low-occupancy second wave. Off-diagonal tiles first,
//    diagonal last (LPT: diag tiles are ~75% cost). Per tile: 4 warps of
//    64x64, 2-stage cp.async, fully unrolled K loop, padded 1152B row stride.
//    Diagonal tiles alias B->A and skip warp 1 entirely (strict lower mirror
//    of warp 2's subtile; weights w0=w3=0.5, w1=0, w2=1). Arithmetic label
//    mask + exp2 epilogue. CTA completing the last tile computes the loss.
// ---------------------------------------------------------------------------
__device__ __forceinline__ void load_chunk(uint32_t sb, int tid, int row0, int col0,
                                           int c, int buf, bool diag) {
    #pragma unroll
    for (int itv = 0; itv < 16; itv++) {
        int slot = itv * 128 + tid;           // 0..2047 16B transfers
        int isB  = slot >> 10;
        if (isB && diag) break;               // diagonal: B tile aliases A tile
        int s2   = slot & 1023;
        int r    = s2 >> 3;                   // row in tile (0..127)
        int g    = s2 & 7;                    // 16B group in 128B row
        const __half* src = g_emb + (size_t)((isB ? col0 : row0) + r) * DSTRIDE
                          + c * KCHUNK + g * 8;
        uint32_t so = sb + buf * 32768 + isB * 16384
                    + (uint32_t)(r * 128) + (uint32_t)((g * 16) ^ ((r & 7) * 16));
        CP_ASYNC16(so, src);
    }
    CP_COMMIT();
}

__global__ void __launch_bounds__(128, 3) gemm_negsum_kernel(
        const int* __restrict__ labels, float* __restrict__ out) {
    extern __shared__ char smem[];
    __shared__ float red[4];
    __shared__ int   s_work;
    __shared__ int   lastflag;
    __shared__ int   labR[BT], labC[BT];
    uint32_t sb = smem_u32(smem);

    int tid  = threadIdx.x;
    int lane = tid & 31;
    int wid  = tid >> 5;

    // lane addressing constants (tile-independent)
    int wm0 = (wid & 1) * 64;
    int wn0 = (wid >> 1) * 64;
    int arow = wm0 + (lane & 15);
    uint32_t a_rowoff = (uint32_t)(arow * 128);
    uint32_t a_xor = (uint32_t)((arow & 7) * 16);
    uint32_t a_colbase = (uint32_t)((lane >> 4) * 16);
    int brow = wn0 + ((lane >> 4) & 1) * 8 + (lane & 7);
    uint32_t b_rowoff = (uint32_t)(brow * 128);
    uint32_t b_xor = (uint32_t)((brow & 7) * 16);
    uint32_t b_colbase = (uint32_t)(((lane >> 3) & 1) * 16);
    int rbase = wm0 + (lane >> 2);
    int cbase = wn0 + (lane & 3) * 2;

    for (;;) {
        if (tid == 0) s_work = atomicAdd(&g_tile, 1);
        __syncthreads();
        int w = s_work;
        if (w >= NTILES) break;

        // work order: off-diagonal tiles first (0..495), diagonal last
        int bi, bj;
        if (w < NOFFD) {
            int t = w, rem = NT - 1;
            bi = 0;
            while (t >= rem) { t -= rem; rem--; bi++; }
            bj = bi + 1 + t;
        } else {
            bi = bj = w - NOFFD;
        }
        int row0 = bi * BT, col0 = bj * BT;
        bool diag = (bi == bj);
        bool skipwarp = diag && (wid == 1);   // strict lower mirror of warp 2

        // labels first: LDG latency overlaps cp.async issue below
        labR[tid] = labels[(row0 + tid) >> 1];
        labC[tid] = labels[(col0 + tid) >> 1];

        load_chunk(sb, tid, row0, col0, 0, 0, diag);
        load_chunk(sb, tid, row0, col0, 1, 1, diag);

        uint32_t acc[4][8][2];                // f16x2 accumulators (64x64)
        #pragma unroll
        for (int i = 0; i < 4; i++)
            #pragma unroll
            for (int j = 0; j < 8; j++) { acc[i][j][0] = 0u; acc[i][j][1] = 0u; }

        #pragma unroll
        for (int c = 0; c < NCHUNKS; c++) {
            const int buf = c & 1;
            if (c == NCHUNKS - 1) { CP_WAIT(0); } else { CP_WAIT(1); }
            __syncthreads();

            if (!skipwarp) {
                uint32_t Ab = sb + (uint32_t)(buf * 32768) + a_rowoff;
                uint32_t Bb = (diag ? sb : sb + 16384u) + (uint32_t)(buf * 32768) + b_rowoff;
                #pragma unroll
                for (int ks = 0; ks < 4; ks++) {
                    uint32_t a[4][4];
                    uint32_t acol = (uint32_t)(ks * 32) + a_colbase;
                    #pragma unroll
                    for (int mt = 0; mt < 4; mt++)
                        ldmatrix_x4(a[mt], Ab + (uint32_t)(mt * 16 * 128) + (acol ^ a_xor));

                    uint32_t b[4][4];
                    uint32_t bcol = (uint32_t)(ks * 32) + b_colbase;
                    #pragma unroll
                    for (int p = 0; p < 4; p++)
                        ldmatrix_x4(b[p], Bb + (uint32_t)(p * 16 * 128) + (bcol ^ b_xor));

                    #pragma unroll
                    for (int mt = 0; mt < 4; mt++)
                        #pragma unroll
                        for (int nt = 0; nt < 8; nt++)
                            mma16816_f16(acc[mt][nt], a[mt],
                                         b[nt >> 1][(nt & 1) * 2 + 0],
                                         b[nt >> 1][(nt & 1) * 2 + 1]);
                }
            }
            if (c + 2 < NCHUNKS) {            // no buffer reuse after last loads
                __syncthreads();
                load_chunk(sb, tid, row0, col0, c + 2, buf, diag);
            }
        }

        // ---- epilogue: label-masked exp2 sum (skipped warp contributes 0) ----
        float lsum = 0.0f;
        if (!skipwarp) {
            float ls[4] = {0.0f, 0.0f, 0.0f, 0.0f};
            #pragma unroll
            for (int mt = 0; mt < 4; mt++)
                #pragma unroll
                for (int e = 0; e < 2; e++) {
                    int lr = labR[rbase + mt * 16 + e * 8];
                    #pragma unroll
                    for (int nt = 0; nt < 8; nt++) {
                        float2 v = __half22float2(*reinterpret_cast<__half2*>(&acc[mt][nt][e]));
                        int c0 = labC[cbase + nt * 8];
                        int c1 = labC[cbase + nt * 8 + 1];
                        float m0 = (lr == c0) ? MASKVAL : v.x;
                        float m1 = (lr == c1) ? MASKVAL : v.y;
                        ls[nt & 3] += exp2_fast(m0) + exp2_fast(m1);
                    }
                }
            lsum = (ls[0] + ls[1]) + (ls[2] + ls[3]);
            // diag weights: w0=w3=0.5 (own-diagonal subtiles), w2=1 (counted
            // once for both mirrors; warp1's mirror was skipped)
            if (diag) lsum *= (wid == 2) ? 1.0f : 0.5f;
        }

        #pragma unroll
        for (int off = 16; off > 0; off >>= 1)
            lsum += __shfl_down_sync(0xffffffffu, lsum, off);
        if (lane == 0) red[wid] = lsum;
        __syncthreads();
        if (tid == 0) {
            atomicAdd(&g_neg, (double)(red[0] + red[1] + red[2] + red[3]));
            __threadfence();
            lastflag = (atomicAdd(&g_cnt, 1) == NTILES - 1);
        }
        __syncthreads();

        // ---- CTA completing the last tile computes the final loss ----
        if (lastflag) {
            __threadfence();
            float negf = (float)g_neg;
            float s = 0.0f;
            for (int p = tid; p < NPAIRS; p += 128) {
                float sp = g_pos[p];
                s += __logf(__expf(sp) + negf) - sp;
            }
            #pragma unroll
            for (int off = 16; off > 0; off >>= 1)
                s += __shfl_down_sync(0xffffffffu, s, off);
            if (lane == 0) red[wid] = s;
            __syncthreads();
            if (tid == 0)
                out[0] = (red[0] + red[1] + red[2] + red[3]) / (float)NPAIRS;
        }
        __syncthreads();   // protect labR/labC/red before next tile
    }
}

// ---------------------------------------------------------------------------
extern "C" void kernel_launch(void* const* d_in, const int* in_sizes, int n_in,
                              void* d_out, int out_size) {
    const float* E      = (const float*)d_in[0];
    const int*   labels = (const int*)d_in[1];
    float*       out    = (float*)d_out;

    const int SMEM_BYTES = 2 * 32768;   // double-buffered A+B tiles
    cudaFuncSetAttribute(gemm_negsum_kernel,
                         cudaFuncAttributeMaxDynamicSharedMemorySize, SMEM_BYTES);

    prep_kernel<<<NPAIRS, 128>>>(E);
    gemm_negsum_kernel<<<NPERSIST, 128, SMEM_BYTES>>>(labels, out);
}